// round 2
// baseline (speedup 1.0000x reference)
#include <cuda_runtime.h>
#include <cstdint>

// Problem constants (fixed by the dataset)
#define NN 100000        // nodes
#define NE 3200000       // edges
#define DF 128           // input feat
#define NH1 128          // layer1 out
#define NH2 64           // layer2 out
#define NG 256           // graphs
#define NC 10            // classes

#define SCAN_B 1024
#define SCAN_NB ((NN + SCAN_B - 1) / SCAN_B)   // 98

// ---------------- scratch (static device memory; no allocation) -------------
__device__ int   g_is64;               // 1 if indices are int64, 0 if int32
__device__ float g_dis[NN];            // deg^-1/2
__device__ int   g_cnt[NN];            // per-dst edge count
__device__ int   g_rowptr[NN + 1];     // CSR row pointers
__device__ int   g_woff[NN];           // scatter write offsets
__device__ int   g_blocksum[SCAN_NB + 1];
__device__ int   g_csr_src[NE];        // CSR column (src) indices
__device__ float g_h1[NN * NH1];       // x @ W1
__device__ float g_r1[NN * NH1];       // relu(gcn1)
__device__ float g_h2[NN * NH2];       // r1 @ W2
__device__ float g_pool[NG * NH2];     // graph sums
__device__ float g_pcnt[NG];           // graph node counts

// index load helper: p holds either int32 or int64 elements
__device__ __forceinline__ int ld_idx(const void* p, long long i, int is64) {
    if (is64) return (int)((const long long*)p)[i];
    return ((const int*)p)[i];
}

// ---------------- kernels ---------------------------------------------------

// Detect index dtype: if data is int64 with values < 2^31, every odd 32-bit
// word of the buffer is zero. For int32 data the odd words are real indices
// (random in [0, 100000)) so the all-zero test fails with overwhelming odds.
__global__ void k_detect(const int* __restrict__ ei_words) {
    if (threadIdx.x == 0) {
        int all0 = 1;
        for (int i = 0; i < 1024; i++) {
            if (ei_words[2 * i + 1] != 0) { all0 = 0; break; }
        }
        g_is64 = all0;
    }
}

__global__ void k_init() {
    int i = blockIdx.x * blockDim.x + threadIdx.x;
    if (i < NN) g_cnt[i] = 0;
    if (i < NG * NH2) g_pool[i] = 0.f;
    if (i < NG) g_pcnt[i] = 0.f;
}

__global__ void k_hist(const void* __restrict__ ei) {
    int e = blockIdx.x * blockDim.x + threadIdx.x;
    int is64 = g_is64;
    if (e < NE) {
        int d = ld_idx(ei, (long long)NE + e, is64);
        atomicAdd(&g_cnt[d], 1);
    }
}

__global__ void k_dis() {
    int i = blockIdx.x * blockDim.x + threadIdx.x;
    if (i < NN) g_dis[i] = rsqrtf((float)g_cnt[i] + 1.0f);
}

// exclusive scan, stage 1: per-block Hillis-Steele
__global__ void k_scan1() {
    __shared__ int s[SCAN_B];
    int t = threadIdx.x;
    int i = blockIdx.x * SCAN_B + t;
    int v = (i < NN) ? g_cnt[i] : 0;
    s[t] = v;
    __syncthreads();
    #pragma unroll
    for (int off = 1; off < SCAN_B; off <<= 1) {
        int add = (t >= off) ? s[t - off] : 0;
        __syncthreads();
        s[t] += add;
        __syncthreads();
    }
    if (i < NN) g_rowptr[i] = s[t] - v;   // exclusive within block
    if (t == SCAN_B - 1) g_blocksum[blockIdx.x] = s[t];
}

// stage 2: scan the 98 block sums (single thread; trivial)
__global__ void k_scan2() {
    if (threadIdx.x == 0 && blockIdx.x == 0) {
        int run = 0;
        for (int b = 0; b < SCAN_NB; b++) {
            int v = g_blocksum[b];
            g_blocksum[b] = run;
            run += v;
        }
    }
}

// stage 3: add block offsets, copy to write-offsets, set rowptr[N]
__global__ void k_scan3() {
    int i = blockIdx.x * blockDim.x + threadIdx.x;
    if (i < NN) {
        int v = g_rowptr[i] + g_blocksum[i >> 10];
        g_rowptr[i] = v;
        g_woff[i] = v;
    }
    if (i == 0) g_rowptr[NN] = NE;
}

__global__ void k_scatter(const void* __restrict__ ei) {
    int e = blockIdx.x * blockDim.x + threadIdx.x;
    int is64 = g_is64;
    if (e < NE) {
        int s = ld_idx(ei, e, is64);
        int d = ld_idx(ei, (long long)NE + e, is64);
        int pos = atomicAdd(&g_woff[d], 1);
        g_csr_src[pos] = s;
    }
}

// C[M,NOUT] = A[M,128] @ W[128,NOUT]  (K fixed at 128)
template <int NOUT>
__global__ void k_gemm(const float* __restrict__ A, const float* __restrict__ W,
                       float* __restrict__ C, int M) {
    constexpr int K = 128, BK = 32, BM = 32;
    constexpr int TN = NOUT / 8;               // cols per thread (16 or 8)
    __shared__ float Ws[BK][NOUT];
    __shared__ float xs[BM][BK + 1];
    int tid = threadIdx.x;                      // 256 threads
    int row_base = blockIdx.x * BM;
    int r  = tid & 31;
    int cg = tid >> 5;
    int c0 = cg * TN;
    float acc[TN];
    #pragma unroll
    for (int j = 0; j < TN; j++) acc[j] = 0.f;

    for (int k0 = 0; k0 < K; k0 += BK) {
        for (int idx = tid; idx < BK * NOUT; idx += 256) {
            int kk = idx / NOUT, cc = idx % NOUT;
            Ws[kk][cc] = W[(k0 + kk) * NOUT + cc];
        }
        for (int idx = tid; idx < BM * BK; idx += 256) {
            int rr = idx >> 5, kk = idx & 31;
            int row = row_base + rr;
            xs[rr][kk] = (row < M) ? A[row * K + k0 + kk] : 0.f;
        }
        __syncthreads();
        #pragma unroll
        for (int k = 0; k < BK; k++) {
            float xv = xs[r][k];
            #pragma unroll
            for (int j = 0; j < TN; j += 4) {
                float4 w4 = *(const float4*)&Ws[k][c0 + j];
                acc[j + 0] += xv * w4.x;
                acc[j + 1] += xv * w4.y;
                acc[j + 2] += xv * w4.z;
                acc[j + 3] += xv * w4.w;
            }
        }
        __syncthreads();
    }
    int row = row_base + r;
    if (row < M) {
        #pragma unroll
        for (int j = 0; j < TN; j += 4) {
            float4 v = make_float4(acc[j], acc[j + 1], acc[j + 2], acc[j + 3]);
            *(float4*)&C[row * NOUT + c0 + j] = v;
        }
    }
}

// Layer-1 aggregation: one warp per dst node, F=128 (float4 per lane), +bias, ReLU
__global__ void k_agg1(const float* __restrict__ b1) {
    int gw   = (blockIdx.x * blockDim.x + threadIdx.x) >> 5;
    int lane = threadIdx.x & 31;
    if (gw >= NN) return;
    int d = gw;
    int s0 = g_rowptr[d], s1 = g_rowptr[d + 1];
    float4 acc = make_float4(0.f, 0.f, 0.f, 0.f);
    const float4* h4 = (const float4*)g_h1;
    for (int j0 = s0; j0 < s1; j0 += 32) {
        int jj = j0 + lane;
        int   s_l = 0;
        float w_l = 0.f;
        if (jj < s1) { s_l = g_csr_src[jj]; w_l = g_dis[s_l]; }
        int m = min(32, s1 - j0);
        for (int k = 0; k < m; k++) {
            int   s = __shfl_sync(0xffffffffu, s_l, k);
            float w = __shfl_sync(0xffffffffu, w_l, k);
            float4 v = h4[s * 32 + lane];
            acc.x += w * v.x; acc.y += w * v.y;
            acc.z += w * v.z; acc.w += w * v.w;
        }
    }
    float dd = g_dis[d], dd2 = dd * dd;
    float4 hv = h4[d * 32 + lane];
    float4 bv = ((const float4*)b1)[lane];
    float4 o;
    o.x = fmaxf(dd * acc.x + dd2 * hv.x + bv.x, 0.f);
    o.y = fmaxf(dd * acc.y + dd2 * hv.y + bv.y, 0.f);
    o.z = fmaxf(dd * acc.z + dd2 * hv.z + bv.z, 0.f);
    o.w = fmaxf(dd * acc.w + dd2 * hv.w + bv.w, 0.f);
    ((float4*)g_r1)[d * 32 + lane] = o;
}

// Layer-2 aggregation fused with mean-pool accumulation: F=64 (float2 per lane)
__global__ void k_agg2_pool(const float* __restrict__ b2,
                            const void* __restrict__ batch) {
    int gw   = (blockIdx.x * blockDim.x + threadIdx.x) >> 5;
    int lane = threadIdx.x & 31;
    if (gw >= NN) return;
    int is64 = g_is64;
    int d = gw;
    int s0 = g_rowptr[d], s1 = g_rowptr[d + 1];
    float2 acc = make_float2(0.f, 0.f);
    const float2* h2 = (const float2*)g_h2;
    for (int j0 = s0; j0 < s1; j0 += 32) {
        int jj = j0 + lane;
        int   s_l = 0;
        float w_l = 0.f;
        if (jj < s1) { s_l = g_csr_src[jj]; w_l = g_dis[s_l]; }
        int m = min(32, s1 - j0);
        for (int k = 0; k < m; k++) {
            int   s = __shfl_sync(0xffffffffu, s_l, k);
            float w = __shfl_sync(0xffffffffu, w_l, k);
            float2 v = h2[s * 32 + lane];
            acc.x += w * v.x; acc.y += w * v.y;
        }
    }
    float dd = g_dis[d], dd2 = dd * dd;
    float2 hv = h2[d * 32 + lane];
    float2 bv = ((const float2*)b2)[lane];
    float ox = dd * acc.x + dd2 * hv.x + bv.x;
    float oy = dd * acc.y + dd2 * hv.y + bv.y;
    int g = ld_idx(batch, d, is64);
    atomicAdd(&g_pool[g * NH2 + lane * 2 + 0], ox);
    atomicAdd(&g_pool[g * NH2 + lane * 2 + 1], oy);
    if (lane == 0) atomicAdd(&g_pcnt[g], 1.0f);
}

// Final: out[g,c] = (pool[g,:]/cnt) @ Wfc + bfc  — 256 blocks x 32 threads
__global__ void k_final(const float* __restrict__ Wfc,
                        const float* __restrict__ bfc,
                        float* __restrict__ out) {
    int g = blockIdx.x;
    int c = threadIdx.x;
    if (c >= NC) return;
    float inv = 1.0f / fmaxf(g_pcnt[g], 1.0f);
    float s = 0.f;
    #pragma unroll 8
    for (int f = 0; f < NH2; f++) {
        s += g_pool[g * NH2 + f] * Wfc[f * NC + c];
    }
    out[g * NC + c] = s * inv + bfc[c];
}

// ---------------- launch -----------------------------------------------------

extern "C" void kernel_launch(void* const* d_in, const int* in_sizes, int n_in,
                              void* d_out, int out_size) {
    const float* x     = (const float*)d_in[0];
    const void*  ei    = d_in[1];
    const void*  batch = d_in[2];
    const float* W1    = (const float*)d_in[3];
    const float* b1    = (const float*)d_in[4];
    const float* W2    = (const float*)d_in[5];
    const float* b2    = (const float*)d_in[6];
    const float* Wfc   = (const float*)d_in[7];
    const float* bfc   = (const float*)d_in[8];
    float* out = (float*)d_out;

    const int TB = 256;

    k_detect<<<1, 32>>>((const int*)ei);
    k_init<<<(NN + TB - 1) / TB, TB>>>();
    k_hist<<<(NE + TB - 1) / TB, TB>>>(ei);
    k_dis<<<(NN + TB - 1) / TB, TB>>>();
    k_scan1<<<SCAN_NB, SCAN_B>>>();
    k_scan2<<<1, 32>>>();
    k_scan3<<<(NN + TB - 1) / TB, TB>>>();
    k_scatter<<<(NE + TB - 1) / TB, TB>>>(ei);

    // GEMM1: h1 = x @ W1
    {
        float* h1p; cudaGetSymbolAddress((void**)&h1p, g_h1);
        k_gemm<NH1><<<(NN + 31) / 32, 256>>>(x, W1, h1p, NN);
    }
    // agg1 + relu -> r1
    k_agg1<<<(NN * 32 + TB - 1) / TB, TB>>>(b1);
    // GEMM2: h2 = r1 @ W2
    {
        float* r1p; cudaGetSymbolAddress((void**)&r1p, g_r1);
        float* h2p; cudaGetSymbolAddress((void**)&h2p, g_h2);
        k_gemm<NH2><<<(NN + 31) / 32, 256>>>(r1p, W2, h2p, NN);
    }
    // agg2 fused with pooling
    k_agg2_pool<<<(NN * 32 + TB - 1) / TB, TB>>>(b2, batch);
    // final FC
    k_final<<<NG, 32>>>(Wfc, bfc, out);
}

// round 3
// speedup vs baseline: 1.0111x; 1.0111x over previous
#include <cuda_runtime.h>
#include <cuda_fp16.h>
#include <cstdint>

// Problem constants (fixed by the dataset)
#define NN 100000        // nodes
#define NE 3200000       // edges
#define DF 128           // input feat
#define NH1 128          // layer1 out
#define NH2 64           // layer2 out
#define NG 256           // graphs
#define NC 10            // classes

#define SCAN_B 1024
#define SCAN_NB ((NN + SCAN_B - 1) / SCAN_B)   // 98

// ---------------- scratch (static device memory; no allocation) -------------
__device__ int   g_is64;               // 1 if indices are int64, 0 if int32
__device__ float g_dis[NN];            // deg^-1/2
__device__ int   g_cnt[NN];            // per-dst edge count
__device__ int   g_rowptr[NN + 1];     // CSR row pointers
__device__ int   g_woff[NN];           // scatter write offsets
__device__ int   g_blocksum[SCAN_NB + 1];
__device__ int   g_csr_src[NE];        // CSR column (src) indices
__device__ uint2 g_h1h[NN * 32];       // x @ W1, fp16 (128 halves = 32 uint2/row)
__device__ float g_r1[NN * NH1];       // relu(gcn1), fp32
__device__ unsigned g_h2h[NN * 32];    // r1 @ W2, fp16 (64 halves = 32 uint/row)
__device__ float g_pool[NG * NH2];     // graph sums
__device__ float g_pcnt[NG];           // graph node counts

// index load helper: p holds either int32 or int64 elements
__device__ __forceinline__ int ld_idx(const void* p, long long i, int is64) {
    if (is64) return (int)((const long long*)p)[i];
    return ((const int*)p)[i];
}

__device__ __forceinline__ void fma_f32x2(unsigned long long& acc,
                                          unsigned long long a,
                                          unsigned long long b) {
    asm("fma.rn.f32x2 %0, %1, %2, %0;" : "+l"(acc) : "l"(a), "l"(b));
}

// ---------------- kernels ---------------------------------------------------

// init scratch + detect index dtype (int64 stored as pairs with zero hi-words)
__global__ void k_init(const int* __restrict__ ei_words) {
    int i = blockIdx.x * blockDim.x + threadIdx.x;
    if (i < NN) g_cnt[i] = 0;
    if (i < NG * NH2) g_pool[i] = 0.f;
    if (i < NG) g_pcnt[i] = 0.f;
    if (blockIdx.x == 0) {
        __shared__ int nz;
        if (threadIdx.x == 0) nz = 0;
        __syncthreads();
        // sample 256 odd 32-bit words; all-zero <=> int64 indices (<2^31)
        if (ei_words[2 * threadIdx.x + 1] != 0) atomicOr(&nz, 1);
        __syncthreads();
        if (threadIdx.x == 0) g_is64 = (nz == 0) ? 1 : 0;
    }
}

__global__ void k_hist(const void* __restrict__ ei) {
    int e = blockIdx.x * blockDim.x + threadIdx.x;
    int is64 = g_is64;
    if (e < NE) {
        int d = ld_idx(ei, (long long)NE + e, is64);
        atomicAdd(&g_cnt[d], 1);
    }
}

// exclusive scan stage 1 (per-block Hillis-Steele) + dis computation
__global__ void k_scan1() {
    __shared__ int s[SCAN_B];
    int t = threadIdx.x;
    int i = blockIdx.x * SCAN_B + t;
    int v = (i < NN) ? g_cnt[i] : 0;
    s[t] = v;
    __syncthreads();
    #pragma unroll
    for (int off = 1; off < SCAN_B; off <<= 1) {
        int add = (t >= off) ? s[t - off] : 0;
        __syncthreads();
        s[t] += add;
        __syncthreads();
    }
    if (i < NN) {
        g_rowptr[i] = s[t] - v;   // exclusive within block
        g_dis[i] = rsqrtf((float)v + 1.0f);
    }
    if (t == SCAN_B - 1) g_blocksum[blockIdx.x] = s[t];
}

__global__ void k_scan2() {
    if (threadIdx.x == 0 && blockIdx.x == 0) {
        int run = 0;
        for (int b = 0; b < SCAN_NB; b++) {
            int v = g_blocksum[b];
            g_blocksum[b] = run;
            run += v;
        }
    }
}

__global__ void k_scan3() {
    int i = blockIdx.x * blockDim.x + threadIdx.x;
    if (i < NN) {
        int v = g_rowptr[i] + g_blocksum[i >> 10];
        g_rowptr[i] = v;
        g_woff[i] = v;
    }
    if (i == 0) g_rowptr[NN] = NE;
}

__global__ void k_scatter(const void* __restrict__ ei) {
    int e = blockIdx.x * blockDim.x + threadIdx.x;
    int is64 = g_is64;
    if (e < NE) {
        int s = ld_idx(ei, e, is64);
        int d = ld_idx(ei, (long long)NE + e, is64);
        int pos = atomicAdd(&g_woff[d], 1);
        g_csr_src[pos] = s;
    }
}

// C[M,NOUT] = A[M,128] @ W[128,NOUT], fp32 math via packed f32x2, half output
template <int NOUT>
__global__ void k_gemm(const float* __restrict__ A, const float* __restrict__ W,
                       __half2* __restrict__ C, int M) {
    constexpr int K = 128, BK = 32, BM = 32;
    constexpr int TN = NOUT / 8;               // cols per thread (16 or 8)
    __shared__ __align__(16) float Ws[BK][NOUT];
    __shared__ float xs[BM][BK + 1];
    int tid = threadIdx.x;                      // 256 threads
    int row_base = blockIdx.x * BM;
    int r  = tid & 31;
    int cg = tid >> 5;
    int c0 = cg * TN;
    unsigned long long acc[TN / 2];
    #pragma unroll
    for (int j = 0; j < TN / 2; j++) acc[j] = 0ull;

    for (int k0 = 0; k0 < K; k0 += BK) {
        for (int idx = tid; idx < BK * NOUT; idx += 256) {
            int kk = idx / NOUT, cc = idx % NOUT;
            Ws[kk][cc] = W[(k0 + kk) * NOUT + cc];
        }
        for (int idx = tid; idx < BM * BK; idx += 256) {
            int rr = idx >> 5, kk = idx & 31;
            int row = row_base + rr;
            xs[rr][kk] = (row < M) ? A[row * K + k0 + kk] : 0.f;
        }
        __syncthreads();
        #pragma unroll
        for (int k = 0; k < BK; k++) {
            float xv = xs[r][k];
            unsigned long long xv2;
            asm("mov.b64 %0, {%1, %1};" : "=l"(xv2) : "f"(xv));
            const unsigned long long* wp =
                (const unsigned long long*)&Ws[k][c0];
            #pragma unroll
            for (int j = 0; j < TN / 2; j++)
                fma_f32x2(acc[j], xv2, wp[j]);
        }
        __syncthreads();
    }
    int row = row_base + r;
    if (row < M) {
        #pragma unroll
        for (int j = 0; j < TN / 2; j++) {
            float lo, hi;
            asm("mov.b64 {%0, %1}, %2;" : "=f"(lo), "=f"(hi) : "l"(acc[j]));
            C[row * (NOUT / 2) + c0 / 2 + j] = __floats2half2_rn(lo, hi);
        }
    }
}

// Layer-1 aggregation: warp/node, fp16 gather (uint2 = 4 halves/lane), fp32 out
__global__ void k_agg1(const float* __restrict__ b1) {
    int gw   = (blockIdx.x * blockDim.x + threadIdx.x) >> 5;
    int lane = threadIdx.x & 31;
    if (gw >= NN) return;
    int d = gw;
    int s0 = g_rowptr[d], s1 = g_rowptr[d + 1];
    float4 acc = make_float4(0.f, 0.f, 0.f, 0.f);
    for (int j0 = s0; j0 < s1; j0 += 32) {
        int jj = j0 + lane;
        int   s_l = 0;
        float w_l = 0.f;
        if (jj < s1) { s_l = g_csr_src[jj]; w_l = g_dis[s_l]; }
        int m = min(32, s1 - j0);
        for (int k = 0; k < m; k++) {
            int   s = __shfl_sync(0xffffffffu, s_l, k);
            float w = __shfl_sync(0xffffffffu, w_l, k);
            uint2 raw = g_h1h[s * 32 + lane];
            float2 fa = __half22float2(*(__half2*)&raw.x);
            float2 fb = __half22float2(*(__half2*)&raw.y);
            acc.x += w * fa.x; acc.y += w * fa.y;
            acc.z += w * fb.x; acc.w += w * fb.y;
        }
    }
    float dd = g_dis[d], dd2 = dd * dd;
    uint2 hraw = g_h1h[d * 32 + lane];
    float2 ha = __half22float2(*(__half2*)&hraw.x);
    float2 hb = __half22float2(*(__half2*)&hraw.y);
    float4 bv = ((const float4*)b1)[lane];
    float4 o;
    o.x = fmaxf(dd * acc.x + dd2 * ha.x + bv.x, 0.f);
    o.y = fmaxf(dd * acc.y + dd2 * ha.y + bv.y, 0.f);
    o.z = fmaxf(dd * acc.z + dd2 * hb.x + bv.z, 0.f);
    o.w = fmaxf(dd * acc.w + dd2 * hb.y + bv.w, 0.f);
    ((float4*)g_r1)[d * 32 + lane] = o;
}

// Layer-2 aggregation fused with mean-pool: fp16 gather (uint = 2 halves/lane)
__global__ void k_agg2_pool(const float* __restrict__ b2,
                            const void* __restrict__ batch) {
    int gw   = (blockIdx.x * blockDim.x + threadIdx.x) >> 5;
    int lane = threadIdx.x & 31;
    if (gw >= NN) return;
    int is64 = g_is64;
    int d = gw;
    int s0 = g_rowptr[d], s1 = g_rowptr[d + 1];
    float2 acc = make_float2(0.f, 0.f);
    for (int j0 = s0; j0 < s1; j0 += 32) {
        int jj = j0 + lane;
        int   s_l = 0;
        float w_l = 0.f;
        if (jj < s1) { s_l = g_csr_src[jj]; w_l = g_dis[s_l]; }
        int m = min(32, s1 - j0);
        for (int k = 0; k < m; k++) {
            int   s = __shfl_sync(0xffffffffu, s_l, k);
            float w = __shfl_sync(0xffffffffu, w_l, k);
            unsigned raw = g_h2h[s * 32 + lane];
            float2 v = __half22float2(*(__half2*)&raw);
            acc.x += w * v.x; acc.y += w * v.y;
        }
    }
    float dd = g_dis[d], dd2 = dd * dd;
    unsigned hraw = g_h2h[d * 32 + lane];
    float2 hv = __half22float2(*(__half2*)&hraw);
    float2 bv = ((const float2*)b2)[lane];
    float ox = dd * acc.x + dd2 * hv.x + bv.x;
    float oy = dd * acc.y + dd2 * hv.y + bv.y;
    int g = ld_idx(batch, d, is64);
    atomicAdd(&g_pool[g * NH2 + lane * 2 + 0], ox);
    atomicAdd(&g_pool[g * NH2 + lane * 2 + 1], oy);
    if (lane == 0) atomicAdd(&g_pcnt[g], 1.0f);
}

// Final: out[g,c] = (pool[g,:]/cnt) @ Wfc + bfc
__global__ void k_final(const float* __restrict__ Wfc,
                        const float* __restrict__ bfc,
                        float* __restrict__ out) {
    int g = blockIdx.x;
    int c = threadIdx.x;
    if (c >= NC) return;
    float inv = 1.0f / fmaxf(g_pcnt[g], 1.0f);
    float s = 0.f;
    #pragma unroll 8
    for (int f = 0; f < NH2; f++) {
        s += g_pool[g * NH2 + f] * Wfc[f * NC + c];
    }
    out[g * NC + c] = s * inv + bfc[c];
}

// ---------------- launch -----------------------------------------------------

extern "C" void kernel_launch(void* const* d_in, const int* in_sizes, int n_in,
                              void* d_out, int out_size) {
    const float* x     = (const float*)d_in[0];
    const void*  ei    = d_in[1];
    const void*  batch = d_in[2];
    const float* W1    = (const float*)d_in[3];
    const float* b1    = (const float*)d_in[4];
    const float* W2    = (const float*)d_in[5];
    const float* b2    = (const float*)d_in[6];
    const float* Wfc   = (const float*)d_in[7];
    const float* bfc   = (const float*)d_in[8];
    float* out = (float*)d_out;

    const int TB = 256;

    k_init<<<(NN + TB - 1) / TB, TB>>>((const int*)ei);
    k_hist<<<(NE + TB - 1) / TB, TB>>>(ei);
    k_scan1<<<SCAN_NB, SCAN_B>>>();
    k_scan2<<<1, 32>>>();
    k_scan3<<<(NN + TB - 1) / TB, TB>>>();
    k_scatter<<<(NE + TB - 1) / TB, TB>>>(ei);

    // GEMM1: h1h = half(x @ W1)
    {
        __half2* h1p; cudaGetSymbolAddress((void**)&h1p, g_h1h);
        k_gemm<NH1><<<(NN + 31) / 32, 256>>>(x, W1, h1p, NN);
    }
    // agg1 + bias + relu -> r1 (fp32)
    k_agg1<<<(NN * 32 + TB - 1) / TB, TB>>>(b1);
    // GEMM2: h2h = half(r1 @ W2)
    {
        float*   r1p; cudaGetSymbolAddress((void**)&r1p, g_r1);
        __half2* h2p; cudaGetSymbolAddress((void**)&h2p, g_h2h);
        k_gemm<NH2><<<(NN + 31) / 32, 256>>>(r1p, W2, h2p, NN);
    }
    // agg2 fused with pooling
    k_agg2_pool<<<(NN * 32 + TB - 1) / TB, TB>>>(b2, batch);
    // final FC
    k_final<<<NG, 32>>>(Wfc, bfc, out);
}

// round 4
// speedup vs baseline: 1.1214x; 1.1091x over previous
#include <cuda_runtime.h>
#include <cuda_fp16.h>
#include <cstdint>

// Problem constants (fixed by the dataset)
#define NN 100000        // nodes
#define NE 3200000       // edges
#define DF 128           // input feat
#define NH1 128          // layer1 out
#define NH2 64           // layer2 out
#define NG 256           // graphs
#define NC 10            // classes

#define SCAN_B 1024
#define SCAN_NB ((NN + SCAN_B - 1) / SCAN_B)   // 98

// ---------------- scratch (static device memory; no allocation) -------------
__device__ int   g_is64;               // 1 if indices are int64, 0 if int32
__device__ float g_dis[NN];            // deg^-1/2
__device__ int   g_cnt[NN];            // per-dst edge count
__device__ int   g_rowptr[NN + 1];     // CSR row pointers
__device__ int   g_woff[NN];           // scatter write offsets
__device__ int   g_blocksum[SCAN_NB + 1];
__device__ int   g_csr_src[NE];        // CSR column (src) indices
__device__ uint2 g_h1h[NN * 32];       // x @ W1, fp16 (128 halves/row)
__device__ uint2 g_r1h[NN * 32];       // relu(gcn1), fp16 (128 halves/row)
__device__ unsigned g_h2h[NN * 32];    // r1 @ W2, fp16 (64 halves/row)
__device__ float g_pool[NG * NH2];     // graph sums
__device__ float g_pcnt[NG];           // graph node counts

// index load helper: p holds either int32 or int64 elements
__device__ __forceinline__ int ld_idx(const void* p, long long i, int is64) {
    if (is64) return (int)((const long long*)p)[i];
    return ((const int*)p)[i];
}

__device__ __forceinline__ void fma_f32x2(unsigned long long& acc,
                                          unsigned long long a,
                                          unsigned long long b) {
    asm("fma.rn.f32x2 %0, %1, %2, %0;" : "+l"(acc) : "l"(a), "l"(b));
}
__device__ __forceinline__ unsigned long long pack2(float lo, float hi) {
    unsigned long long r;
    asm("mov.b64 %0, {%1, %2};" : "=l"(r) : "f"(lo), "f"(hi));
    return r;
}
__device__ __forceinline__ unsigned long long dup2(float v) {
    unsigned long long r;
    asm("mov.b64 %0, {%1, %1};" : "=l"(r) : "f"(v));
    return r;
}
__device__ __forceinline__ void unpack2(unsigned long long p, float& lo, float& hi) {
    asm("mov.b64 {%0, %1}, %2;" : "=f"(lo), "=f"(hi) : "l"(p));
}

__device__ __forceinline__ float ldconv(const float* p) { return *p; }
__device__ __forceinline__ float ldconv(const __half* p) { return __half2float(*p); }

// ---------------- setup kernels ---------------------------------------------

__global__ void k_init(const int* __restrict__ ei_words) {
    int i = blockIdx.x * blockDim.x + threadIdx.x;
    if (i < NN) g_cnt[i] = 0;
    if (i < NG * NH2) g_pool[i] = 0.f;
    if (i < NG) g_pcnt[i] = 0.f;
    if (blockIdx.x == 0) {
        __shared__ int nz;
        if (threadIdx.x == 0) nz = 0;
        __syncthreads();
        if (ei_words[2 * threadIdx.x + 1] != 0) atomicOr(&nz, 1);
        __syncthreads();
        if (threadIdx.x == 0) g_is64 = (nz == 0) ? 1 : 0;
    }
}

__global__ void k_hist(const void* __restrict__ ei) {
    int e = blockIdx.x * blockDim.x + threadIdx.x;
    int is64 = g_is64;
    if (e < NE) {
        int d = ld_idx(ei, (long long)NE + e, is64);
        atomicAdd(&g_cnt[d], 1);
    }
}

__global__ void k_scan1() {
    __shared__ int s[SCAN_B];
    int t = threadIdx.x;
    int i = blockIdx.x * SCAN_B + t;
    int v = (i < NN) ? g_cnt[i] : 0;
    s[t] = v;
    __syncthreads();
    #pragma unroll
    for (int off = 1; off < SCAN_B; off <<= 1) {
        int add = (t >= off) ? s[t - off] : 0;
        __syncthreads();
        s[t] += add;
        __syncthreads();
    }
    if (i < NN) {
        g_rowptr[i] = s[t] - v;
        g_dis[i] = rsqrtf((float)v + 1.0f);
    }
    if (t == SCAN_B - 1) g_blocksum[blockIdx.x] = s[t];
}

__global__ void k_scan2() {
    if (threadIdx.x == 0 && blockIdx.x == 0) {
        int run = 0;
        for (int b = 0; b < SCAN_NB; b++) {
            int v = g_blocksum[b];
            g_blocksum[b] = run;
            run += v;
        }
    }
}

__global__ void k_scan3() {
    int i = blockIdx.x * blockDim.x + threadIdx.x;
    if (i < NN) {
        int v = g_rowptr[i] + g_blocksum[i >> 10];
        g_rowptr[i] = v;
        g_woff[i] = v;
    }
    if (i == 0) g_rowptr[NN] = NE;
}

__global__ void k_scatter(const void* __restrict__ ei) {
    int e = blockIdx.x * blockDim.x + threadIdx.x;
    int is64 = g_is64;
    if (e < NE) {
        int s = ld_idx(ei, e, is64);
        int d = ld_idx(ei, (long long)NE + e, is64);
        int pos = atomicAdd(&g_woff[d], 1);
        g_csr_src[pos] = s;
    }
}

// ---------------- register-tiled GEMM ----------------------------------------
// C[M,NOUT] = A[M,128] @ W[128,NOUT], fp32 math (f32x2), half2 output.
// BM=128 rows/block, BK=16. Thread grid: 16 row-groups x (NOUT/8) col-groups.
// Each thread: 8 rows x 8 cols (cols split into two 4-wide panels).
template <int NOUT, typename AT>
__global__ void k_gemm(const AT* __restrict__ A, const float* __restrict__ W,
                       __half2* __restrict__ C, int M) {
    constexpr int K = 128, BK = 16, BM = 128;
    constexpr int COLG = NOUT / 8;            // 16 or 8
    constexpr int NTH = COLG * 16;            // 256 or 128
    constexpr int XS = BM + 4;                // pad: keeps 16B align, spreads banks
    __shared__ __align__(16) float xs[BK][XS];
    __shared__ __align__(16) float Ws[BK][NOUT];
    int tid = threadIdx.x;
    int tx = tid % COLG;
    int ty = tid / COLG;                      // 0..15
    int rb = blockIdx.x * BM;

    unsigned long long acc[4][8];             // [row-pair][col]; lanes = 2 rows
    #pragma unroll
    for (int i = 0; i < 4; i++)
        #pragma unroll
        for (int j = 0; j < 8; j++) acc[i][j] = 0ull;

    for (int k0 = 0; k0 < K; k0 += BK) {
        #pragma unroll 2
        for (int idx = tid; idx < BK * NOUT; idx += NTH) {
            int kk = idx / NOUT, cc = idx % NOUT;
            Ws[kk][cc] = W[(k0 + kk) * NOUT + cc];
        }
        #pragma unroll 2
        for (int idx = tid; idx < BM * BK; idx += NTH) {
            int rr = idx >> 4, kk = idx & 15;
            int row = rb + rr;
            xs[kk][rr] = (row < M) ? ldconv(&A[row * K + k0 + kk]) : 0.f;
        }
        __syncthreads();
        #pragma unroll
        for (int k = 0; k < BK; k++) {
            float4 xa = *(const float4*)&xs[k][ty * 8];
            float4 xb = *(const float4*)&xs[k][ty * 8 + 4];
            unsigned long long xp[4];
            xp[0] = pack2(xa.x, xa.y);
            xp[1] = pack2(xa.z, xa.w);
            xp[2] = pack2(xb.x, xb.y);
            xp[3] = pack2(xb.z, xb.w);
            float4 wa = *(const float4*)&Ws[k][tx * 4];
            float4 wb = *(const float4*)&Ws[k][NOUT / 2 + tx * 4];
            unsigned long long wd[8];
            wd[0] = dup2(wa.x); wd[1] = dup2(wa.y);
            wd[2] = dup2(wa.z); wd[3] = dup2(wa.w);
            wd[4] = dup2(wb.x); wd[5] = dup2(wb.y);
            wd[6] = dup2(wb.z); wd[7] = dup2(wb.w);
            #pragma unroll
            for (int i = 0; i < 4; i++)
                #pragma unroll
                for (int j = 0; j < 8; j++)
                    fma_f32x2(acc[i][j], xp[i], wd[j]);
        }
        __syncthreads();
    }

    // epilogue: acc[i][j] lanes = rows (2i, 2i+1), col panels at tx*4 / NOUT/2+tx*4
    #pragma unroll
    for (int i = 0; i < 4; i++) {
        int r0 = rb + ty * 8 + 2 * i;
        #pragma unroll
        for (int rr = 0; rr < 2; rr++) {
            int row = r0 + rr;
            if (row >= M) continue;
            float v[8];
            #pragma unroll
            for (int j = 0; j < 8; j++) {
                float lo, hi;
                unpack2(acc[i][j], lo, hi);
                v[j] = rr ? hi : lo;
            }
            __half2* cp = &C[(long long)row * (NOUT / 2)];
            cp[tx * 2 + 0] = __floats2half2_rn(v[0], v[1]);
            cp[tx * 2 + 1] = __floats2half2_rn(v[2], v[3]);
            cp[NOUT / 4 + tx * 2 + 0] = __floats2half2_rn(v[4], v[5]);
            cp[NOUT / 4 + tx * 2 + 1] = __floats2half2_rn(v[6], v[7]);
        }
    }
}

// ---------------- aggregation kernels ----------------------------------------

// Layer-1 aggregation: warp/node, fp16 gather (uint2 = 4 halves/lane), fp16 out
__global__ void k_agg1(const float* __restrict__ b1) {
    int gw   = (blockIdx.x * blockDim.x + threadIdx.x) >> 5;
    int lane = threadIdx.x & 31;
    if (gw >= NN) return;
    int d = gw;
    int s0 = g_rowptr[d], s1 = g_rowptr[d + 1];
    float4 acc = make_float4(0.f, 0.f, 0.f, 0.f);
    for (int j0 = s0; j0 < s1; j0 += 32) {
        int jj = j0 + lane;
        int   s_l = 0;
        float w_l = 0.f;
        if (jj < s1) { s_l = g_csr_src[jj]; w_l = g_dis[s_l]; }
        int m = min(32, s1 - j0);
        for (int k = 0; k < m; k++) {
            int   s = __shfl_sync(0xffffffffu, s_l, k);
            float w = __shfl_sync(0xffffffffu, w_l, k);
            uint2 raw = g_h1h[s * 32 + lane];
            float2 fa = __half22float2(*(__half2*)&raw.x);
            float2 fb = __half22float2(*(__half2*)&raw.y);
            acc.x += w * fa.x; acc.y += w * fa.y;
            acc.z += w * fb.x; acc.w += w * fb.y;
        }
    }
    float dd = g_dis[d], dd2 = dd * dd;
    uint2 hraw = g_h1h[d * 32 + lane];
    float2 ha = __half22float2(*(__half2*)&hraw.x);
    float2 hb = __half22float2(*(__half2*)&hraw.y);
    float4 bv = ((const float4*)b1)[lane];
    float ox = fmaxf(dd * acc.x + dd2 * ha.x + bv.x, 0.f);
    float oy = fmaxf(dd * acc.y + dd2 * ha.y + bv.y, 0.f);
    float oz = fmaxf(dd * acc.z + dd2 * hb.x + bv.z, 0.f);
    float ow = fmaxf(dd * acc.w + dd2 * hb.y + bv.w, 0.f);
    uint2 o;
    *(__half2*)&o.x = __floats2half2_rn(ox, oy);
    *(__half2*)&o.y = __floats2half2_rn(oz, ow);
    g_r1h[d * 32 + lane] = o;
}

// Layer-2 aggregation fused with mean-pool: fp16 gather (uint = 2 halves/lane)
__global__ void k_agg2_pool(const float* __restrict__ b2,
                            const void* __restrict__ batch) {
    int gw   = (blockIdx.x * blockDim.x + threadIdx.x) >> 5;
    int lane = threadIdx.x & 31;
    if (gw >= NN) return;
    int is64 = g_is64;
    int d = gw;
    int s0 = g_rowptr[d], s1 = g_rowptr[d + 1];
    float2 acc = make_float2(0.f, 0.f);
    for (int j0 = s0; j0 < s1; j0 += 32) {
        int jj = j0 + lane;
        int   s_l = 0;
        float w_l = 0.f;
        if (jj < s1) { s_l = g_csr_src[jj]; w_l = g_dis[s_l]; }
        int m = min(32, s1 - j0);
        for (int k = 0; k < m; k++) {
            int   s = __shfl_sync(0xffffffffu, s_l, k);
            float w = __shfl_sync(0xffffffffu, w_l, k);
            unsigned raw = g_h2h[s * 32 + lane];
            float2 v = __half22float2(*(__half2*)&raw);
            acc.x += w * v.x; acc.y += w * v.y;
        }
    }
    float dd = g_dis[d], dd2 = dd * dd;
    unsigned hraw = g_h2h[d * 32 + lane];
    float2 hv = __half22float2(*(__half2*)&hraw);
    float2 bv = ((const float2*)b2)[lane];
    float ox = dd * acc.x + dd2 * hv.x + bv.x;
    float oy = dd * acc.y + dd2 * hv.y + bv.y;
    int g = ld_idx(batch, d, is64);
    atomicAdd(&g_pool[g * NH2 + lane * 2 + 0], ox);
    atomicAdd(&g_pool[g * NH2 + lane * 2 + 1], oy);
    if (lane == 0) atomicAdd(&g_pcnt[g], 1.0f);
}

// Final: out[g,c] = (pool[g,:]/cnt) @ Wfc + bfc
__global__ void k_final(const float* __restrict__ Wfc,
                        const float* __restrict__ bfc,
                        float* __restrict__ out) {
    int g = blockIdx.x;
    int c = threadIdx.x;
    if (c >= NC) return;
    float inv = 1.0f / fmaxf(g_pcnt[g], 1.0f);
    float s = 0.f;
    #pragma unroll 8
    for (int f = 0; f < NH2; f++) {
        s += g_pool[g * NH2 + f] * Wfc[f * NC + c];
    }
    out[g * NC + c] = s * inv + bfc[c];
}

// ---------------- launch -----------------------------------------------------

extern "C" void kernel_launch(void* const* d_in, const int* in_sizes, int n_in,
                              void* d_out, int out_size) {
    const float* x     = (const float*)d_in[0];
    const void*  ei    = d_in[1];
    const void*  batch = d_in[2];
    const float* W1    = (const float*)d_in[3];
    const float* b1    = (const float*)d_in[4];
    const float* W2    = (const float*)d_in[5];
    const float* b2    = (const float*)d_in[6];
    const float* Wfc   = (const float*)d_in[7];
    const float* bfc   = (const float*)d_in[8];
    float* out = (float*)d_out;

    const int TB = 256;
    const int GB = (NN + 127) / 128;   // 782 GEMM blocks

    k_init<<<(NN + TB - 1) / TB, TB>>>((const int*)ei);
    k_hist<<<(NE + TB - 1) / TB, TB>>>(ei);
    k_scan1<<<SCAN_NB, SCAN_B>>>();
    k_scan2<<<1, 32>>>();
    k_scan3<<<(NN + TB - 1) / TB, TB>>>();
    k_scatter<<<(NE + TB - 1) / TB, TB>>>(ei);

    // GEMM1: h1h = half(x @ W1)
    {
        __half2* h1p; cudaGetSymbolAddress((void**)&h1p, g_h1h);
        k_gemm<NH1, float><<<GB, 256>>>(x, W1, h1p, NN);
    }
    // agg1 + bias + relu -> r1h (fp16)
    k_agg1<<<(NN * 32 + TB - 1) / TB, TB>>>(b1);
    // GEMM2: h2h = half(r1h @ W2)
    {
        __half*  r1p; cudaGetSymbolAddress((void**)&r1p, g_r1h);
        __half2* h2p; cudaGetSymbolAddress((void**)&h2p, g_h2h);
        k_gemm<NH2, __half><<<GB, 128>>>(r1p, W2, h2p, NN);
    }
    // agg2 fused with pooling
    k_agg2_pool<<<(NN * 32 + TB - 1) / TB, TB>>>(b2, batch);
    // final FC
    k_final<<<NG, 32>>>(Wfc, bfc, out);
}